// round 15
// baseline (speedup 1.0000x reference)
#include <cuda_runtime.h>

typedef unsigned long long u64;

#define Bn 16
#define Hn 1024
#define Tn 4096
#define CDn 8
#define CSn 1024

#define THREADS 256
#define TT 256
#define TILES_PER_B (Tn / TT)        // 16
#define NBLK (Bn * TILES_PER_B)      // 256

#define OUT_N ((size_t)Bn * Hn * Tn)
#define LOSS_OFF (OUT_N)
#define IDX_OFF (OUT_N + 2)
#define PROJ_OFF (OUT_N + 2 + (size_t)Bn * Tn)

__device__ float g_losspart[NBLK];
__device__ unsigned int g_count;

__device__ __forceinline__ u64 pack2(float x, float y) {
    u64 r; asm("mov.b64 %0, {%1,%2};" : "=l"(r) : "f"(x), "f"(y)); return r;
}
__device__ __forceinline__ void unpack2(u64 v, float& x, float& y) {
    asm("mov.b64 {%0,%1}, %2;" : "=f"(x), "=f"(y) : "l"(v));
}
__device__ __forceinline__ u64 ffma2(u64 a, u64 b, u64 c) {
    u64 d; asm("fma.rn.f32x2 %0, %1, %2, %3;" : "=l"(d) : "l"(a), "l"(b), "l"(c)); return d;
}
__device__ __forceinline__ void pfL2(const void* p) {
    asm volatile("prefetch.global.L2 [%0];" :: "l"(p));
}

// smem float layout (phased reuse):
//   [0,16384)     big : wdup (8192 u64, phase1) | cbs(8192)+cb2s(1024) (phase2)
//                       | wdup (wos dup, phase3)
//   [16384,18432) xfer : proj handoff 256t x 8d (phase1->2) | bdup (1024 u64, phase3)
//   [18432,18688) sbestg : float2[128]
//   [18688,18944) sidxg  : int2[128]
//   [18944,19200) sidxf  : int2[128]
//   [19200,19204) wsum
#define SMEM_FLOATS 19204
extern __shared__ float smem[];

__global__ __launch_bounds__(THREADS, 2) void main_kernel(
    const float* __restrict__ hid,   // [B,H,T]
    const float* __restrict__ w_in,  // [CD,H]
    const float* __restrict__ b_in,  // [CD]
    const float* __restrict__ w_out, // [H,CD]
    const float* __restrict__ b_out, // [H]
    const float* __restrict__ cb,    // [CS,CD]
    float* __restrict__ dout)
{
    float*  big    = smem;
    u64*    wdup   = reinterpret_cast<u64*>(smem);          // 8192 u64
    float*  xfer   = smem + 16384;
    u64*    bdup   = reinterpret_cast<u64*>(smem + 16384);  // 1024 u64
    float2* sbestg = reinterpret_cast<float2*>(smem + 18432);
    int2*   sidxg  = reinterpret_cast<int2*>(smem + 18688);
    int2*   sidxf  = reinterpret_cast<int2*>(smem + 18944);
    float*  wsum   = smem + 19200;
    __shared__ unsigned int s_is_last;

    const int tid = threadIdx.x;
    const int blk = blockIdx.x;
    const int b   = blk >> 4;
    const int t0  = (blk & 15) << 8;

    // ---- fill wdup[h*8+d] = (w_in[d][h], w_in[d][h]) ----------------------
    {
        const float4* wiv = reinterpret_cast<const float4*>(w_in);
#pragma unroll
        for (int k = 0; k < 8; k++) {
            int i4 = tid + THREADS * k;          // float4 index in [0,2048)
            float4 w = __ldg(wiv + i4);
            int d  = i4 >> 8;                    // 256 float4 per d-row
            int h4 = (i4 << 2) & 1023;
            wdup[(h4    ) * 8 + d] = pack2(w.x, w.x);
            wdup[(h4 + 1) * 8 + d] = pack2(w.y, w.y);
            wdup[(h4 + 2) * 8 + d] = pack2(w.z, w.z);
            wdup[(h4 + 3) * 8 + d] = pack2(w.w, w.w);
        }
    }
    __syncthreads();

    // ===== Phase 1: proj. thread = t-pair (2t) x d-half (4d), t-packed =====
    {
        const int u  = tid & 127;         // t-pair index: t = 2u, 2u+1
        const int dh = tid >> 7;          // 0: d0-3, 1: d4-7
        const bool dopf = (dh == 0);      // warp-uniform
        const int dbase = 4 * dh;
        u64 a0 = 0ULL, a1 = 0ULL, a2 = 0ULL, a3 = 0ULL;  // (t0,t1) per d
        const float* xp = hid + (size_t)b * Hn * Tn + (t0 + 2 * u);
        const u64* wrow = wdup + dbase;

#define PF 32
#pragma unroll 8
        for (int h = 0; h < Hn - PF; h++) {
            if (dopf) pfL2(xp + (size_t)(h + PF) * Tn);
            u64 xd = __ldg(reinterpret_cast<const u64*>(xp + (size_t)h * Tn)); // (x_t0, x_t1)
            ulonglong2 wA = *reinterpret_cast<const ulonglong2*>(wrow + h * 8);
            ulonglong2 wB = *reinterpret_cast<const ulonglong2*>(wrow + h * 8 + 2);
            a0 = ffma2(wA.x, xd, a0);
            a1 = ffma2(wA.y, xd, a1);
            a2 = ffma2(wB.x, xd, a2);
            a3 = ffma2(wB.y, xd, a3);
        }
#pragma unroll 8
        for (int h = Hn - PF; h < Hn; h++) {
            u64 xd = __ldg(reinterpret_cast<const u64*>(xp + (size_t)h * Tn));
            ulonglong2 wA = *reinterpret_cast<const ulonglong2*>(wrow + h * 8);
            ulonglong2 wB = *reinterpret_cast<const ulonglong2*>(wrow + h * 8 + 2);
            a0 = ffma2(wA.x, xd, a0);
            a1 = ffma2(wA.y, xd, a1);
            a2 = ffma2(wB.x, xd, a2);
            a3 = ffma2(wB.y, xd, a3);
        }
#undef PF
        float pA[4], pB[4];                // pA = t0 (d0..3 of half), pB = t1
        unpack2(a0, pA[0], pB[0]);
        unpack2(a1, pA[1], pB[1]);
        unpack2(a2, pA[2], pB[2]);
        unpack2(a3, pA[3], pB[3]);
        __syncthreads();                   // wdup reads done before xfer overwrite? (xfer separate region; sync for cbs overwrite below)
#pragma unroll
        for (int d = 0; d < 4; d++) {
            float bb = __ldg(b_in + dbase + d);
            float vA = __fadd_rn(pA[d], bb);
            float vB = __fadd_rn(pB[d], bb);
            xfer[(2 * u) * CDn + dbase + d]     = vA;
            xfer[(2 * u + 1) * CDn + dbase + d] = vB;
            __stcs(reinterpret_cast<float2*>(
                       dout + PROJ_OFF + ((size_t)b * CDn + dbase + d) * Tn + (t0 + 2 * u)),
                   make_float2(vA, vB));
        }
    }

    // ---- normalized codebook into cbs/cb2s (identical math) ----------------
    float* cbs  = big;
    float* cb2s = big + CSn * CDn;
#pragma unroll
    for (int k = 0; k < 4; k++) {
        int j = tid + THREADS * k;
        const float4* cr = reinterpret_cast<const float4*>(cb + j * CDn);
        float4 ca = __ldg(cr), cbv4 = __ldg(cr + 1);
        float v[CDn] = {ca.x, ca.y, ca.z, ca.w, cbv4.x, cbv4.y, cbv4.z, cbv4.w};
        float s = 0.f;
#pragma unroll
        for (int d = 0; d < CDn; d++) s = __fadd_rn(s, __fmul_rn(v[d], v[d]));
        float m = fmaxf(__fsqrt_rn(s), 1e-12f);
        float cd[CDn];
        float s2 = 0.f;
#pragma unroll
        for (int d = 0; d < CDn; d++) {
            cd[d] = __fdiv_rn(v[d], m);
            s2 = __fadd_rn(s2, __fmul_rn(cd[d], cd[d]));
        }
        float4* dst = reinterpret_cast<float4*>(cbs + j * CDn);
        dst[0] = make_float4(cd[0], cd[1], cd[2], cd[3]);
        dst[1] = make_float4(cd[4], cd[5], cd[6], cd[7]);
        cb2s[j] = s2;
    }
    __syncthreads();

    // ===== Phase 2: argmax. 2 t/thread, j split 2-way (R13 verbatim) =======
    const int pr  = tid & 127;
    const int grp = tid >> 7;

    float l20, l21;
    u64 ed0[4], ed1[4];
    float p0[CDn], p1[CDn];
    {
        const float4* x0 = reinterpret_cast<const float4*>(xfer + (2 * pr) * CDn);
        const float4* x1 = reinterpret_cast<const float4*>(xfer + (2 * pr + 1) * CDn);
        float4 a0 = x0[0], a1 = x0[1], c0 = x1[0], c1 = x1[1];
        p0[0]=a0.x; p0[1]=a0.y; p0[2]=a0.z; p0[3]=a0.w;
        p0[4]=a1.x; p0[5]=a1.y; p0[6]=a1.z; p0[7]=a1.w;
        p1[0]=c0.x; p1[1]=c0.y; p1[2]=c0.z; p1[3]=c0.w;
        p1[4]=c1.x; p1[5]=c1.y; p1[6]=c1.z; p1[7]=c1.w;

        float l2r0 = 0.f, l2r1 = 0.f;
#pragma unroll
        for (int d = 0; d < CDn; d++) {
            l2r0 = __fadd_rn(l2r0, __fmul_rn(p0[d], p0[d]));
            l2r1 = __fadd_rn(l2r1, __fmul_rn(p1[d], p1[d]));
        }
        float den0 = fmaxf(__fsqrt_rn(l2r0), 1e-12f);
        float den1 = fmaxf(__fsqrt_rn(l2r1), 1e-12f);
        float e0[CDn], e1[CDn];
        l20 = 0.f; l21 = 0.f;
#pragma unroll
        for (int d = 0; d < CDn; d++) {
            e0[d] = __fdiv_rn(p0[d], den0);
            e1[d] = __fdiv_rn(p1[d], den1);
            l20 = __fadd_rn(l20, __fmul_rn(e0[d], e0[d]));
            l21 = __fadd_rn(l21, __fmul_rn(e1[d], e1[d]));
        }
#pragma unroll
        for (int q = 0; q < 4; q++) {
            ed0[q] = pack2(e0[2 * q], e0[2 * q + 1]);
            ed1[q] = pack2(e1[2 * q], e1[2 * q + 1]);
        }
    }

    const int jstart = grp << 9;
    float best0 = -3.402823466e38f, best1 = -3.402823466e38f;
    int i0 = jstart, i1 = jstart;
#pragma unroll 2
    for (int j = jstart; j < jstart + 512; j += 2) {
        const ulonglong2* crA = reinterpret_cast<const ulonglong2*>(cbs + j * CDn);
        ulonglong2 caA = crA[0], cbA = crA[1];
        ulonglong2 caB = crA[2], cbB = crA[3];
        float2 cb2p = *reinterpret_cast<const float2*>(cb2s + j);

        // ---- j ----
        {
            u64 a = ffma2(ed0[0], caA.x, 0ULL);
            a = ffma2(ed0[1], caA.y, a); a = ffma2(ed0[2], cbA.x, a); a = ffma2(ed0[3], cbA.y, a);
            float alo, ahi; unpack2(a, alo, ahi);
            float dot0 = __fadd_rn(alo, ahi);
            float s0 = __fsub_rn(cb2p.x, __fmaf_rn(-2.f, dot0, l20));
            if (s0 > best0) { best0 = s0; i0 = j; }

            u64 bq = ffma2(ed1[0], caA.x, 0ULL);
            bq = ffma2(ed1[1], caA.y, bq); bq = ffma2(ed1[2], cbA.x, bq); bq = ffma2(ed1[3], cbA.y, bq);
            float blo, bhi; unpack2(bq, blo, bhi);
            float dot1 = __fadd_rn(blo, bhi);
            float s1 = __fsub_rn(cb2p.x, __fmaf_rn(-2.f, dot1, l21));
            if (s1 > best1) { best1 = s1; i1 = j; }
        }
        // ---- j + 1 ----
        {
            u64 a = ffma2(ed0[0], caB.x, 0ULL);
            a = ffma2(ed0[1], caB.y, a); a = ffma2(ed0[2], cbB.x, a); a = ffma2(ed0[3], cbB.y, a);
            float alo, ahi; unpack2(a, alo, ahi);
            float dot0 = __fadd_rn(alo, ahi);
            float s0 = __fsub_rn(cb2p.y, __fmaf_rn(-2.f, dot0, l20));
            if (s0 > best0) { best0 = s0; i0 = j + 1; }

            u64 bq = ffma2(ed1[0], caB.x, 0ULL);
            bq = ffma2(ed1[1], caB.y, bq); bq = ffma2(ed1[2], cbB.x, bq); bq = ffma2(ed1[3], cbB.y, bq);
            float blo, bhi; unpack2(bq, blo, bhi);
            float dot1 = __fadd_rn(blo, bhi);
            float s1 = __fsub_rn(cb2p.y, __fmaf_rn(-2.f, dot1, l21));
            if (s1 > best1) { best1 = s1; i1 = j + 1; }
        }
    }
    if (grp) {
        sbestg[pr] = make_float2(best0, best1);
        sidxg[pr]  = make_int2(i0, i1);
    }
    __syncthreads();

    // ---- fill wdup (w_out dup) + bdup, then g0 combine/epilogue ------------
    {
        const float4* wov = reinterpret_cast<const float4*>(w_out);
#pragma unroll
        for (int k = 0; k < 8; k++) {
            int i4 = tid + THREADS * k;          // float4 idx in [0,2048)
            float4 w = __ldg(wov + i4);
            int h  = i4 >> 1;
            int ds = (i4 & 1) * 4;
            wdup[h * 8 + ds    ] = pack2(w.x, w.x);
            wdup[h * 8 + ds + 1] = pack2(w.y, w.y);
            wdup[h * 8 + ds + 2] = pack2(w.z, w.z);
            wdup[h * 8 + ds + 3] = pack2(w.w, w.w);
        }
#pragma unroll
        for (int k = 0; k < 4; k++) {
            int i = tid + THREADS * k;
            float bv = b_out[i];
            bdup[i] = pack2(bv, bv);
        }
    }

    if (grp == 0) {
        // combine ascending-j (grp0 local, then grp1): strict > keeps first max
        {
            float2 bb = sbestg[pr];
            int2   ii = sidxg[pr];
            if (bb.x > best0) { best0 = bb.x; i0 = ii.x; }
            if (bb.y > best1) { best1 = bb.y; i1 = ii.y; }
        }
        sidxf[pr] = make_int2(i0, i1);
        __stcs(reinterpret_cast<float2*>(dout + IDX_OFF + (size_t)b * Tn + t0 + 2 * pr),
               make_float2((float)i0, (float)i1));

        // loss partial: p kept in regs, q from codebook
        const float4* cbv = reinterpret_cast<const float4*>(cb);
        float4 qa0 = __ldg(cbv + i0 * 2), qb0 = __ldg(cbv + i0 * 2 + 1);
        float4 qa1 = __ldg(cbv + i1 * 2), qb1 = __ldg(cbv + i1 * 2 + 1);
        float q0[CDn] = {qa0.x, qa0.y, qa0.z, qa0.w, qb0.x, qb0.y, qb0.z, qb0.w};
        float q1[CDn] = {qa1.x, qa1.y, qa1.z, qa1.w, qb1.x, qb1.y, qb1.z, qb1.w};

        float ls = 0.f;
#pragma unroll
        for (int d = 0; d < CDn; d++) {
            float a = p0[d] - q0[d]; ls = __fmaf_rn(a, a, ls);
            float c = p1[d] - q1[d]; ls = __fmaf_rn(c, c, ls);
        }
#pragma unroll
        for (int o = 16; o; o >>= 1) ls += __shfl_xor_sync(0xFFFFFFFFu, ls, o);
        if ((tid & 31) == 0) wsum[tid >> 5] = ls;
    }
    __syncthreads();
    if (tid == 0) g_losspart[blk] = (wsum[0] + wsum[1]) + (wsum[2] + wsum[3]);

    // ===== Phase 3: out. 2 t/thread t-packed, h split 2-way ================
    {
        int2 ji = sidxf[pr];
        const float4* cbv = reinterpret_cast<const float4*>(cb);
        float4 qa0 = __ldg(cbv + ji.x * 2), qb0 = __ldg(cbv + ji.x * 2 + 1);
        float4 qa1 = __ldg(cbv + ji.y * 2), qb1 = __ldg(cbv + ji.y * 2 + 1);

        u64 qp[8];                       // (q_d(t0), q_d(t1)) per d
        qp[0] = pack2(qa0.x, qa1.x); qp[1] = pack2(qa0.y, qa1.y);
        qp[2] = pack2(qa0.z, qa1.z); qp[3] = pack2(qa0.w, qa1.w);
        qp[4] = pack2(qb0.x, qb1.x); qp[5] = pack2(qb0.y, qb1.y);
        qp[6] = pack2(qb0.z, qb1.z); qp[7] = pack2(qb0.w, qb1.w);

        u64* outbase = reinterpret_cast<u64*>(dout + (size_t)b * Hn * Tn + (t0 + 2 * pr));
        const int hbase = grp << 9;
#pragma unroll 4
        for (int hh = 0; hh < 512; hh++) {
            int h = hbase + hh;
            const ulonglong2* wr = reinterpret_cast<const ulonglong2*>(wdup + h * 8);
            ulonglong2 w0 = wr[0], w1 = wr[1], w2 = wr[2], w3 = wr[3];
            u64 acc = bdup[h];           // (bias, bias) seeds both t chains

            acc = ffma2(qp[0], w0.x, acc); acc = ffma2(qp[1], w0.y, acc);
            acc = ffma2(qp[2], w1.x, acc); acc = ffma2(qp[3], w1.y, acc);
            acc = ffma2(qp[4], w2.x, acc); acc = ffma2(qp[5], w2.y, acc);
            acc = ffma2(qp[6], w3.x, acc); acc = ffma2(qp[7], w3.y, acc);

            __stcs(outbase + (size_t)h * (Tn / 2), acc);
        }
    }

    // ---- last block finalizes loss mean ------------------------------------
    __syncthreads();
    if (tid == 0) {
        __threadfence();
        unsigned int c = atomicAdd(&g_count, 1u);
        s_is_last = (c == NBLK - 1) ? 1u : 0u;
        if (s_is_last) g_count = 0;
    }
    __syncthreads();
    if (s_is_last) {
        float v = __ldcg(g_losspart + tid);
#pragma unroll
        for (int o = 16; o; o >>= 1) v += __shfl_xor_sync(0xFFFFFFFFu, v, o);
        __syncthreads();
        if ((tid & 31) == 0) sbestg[tid >> 5].x = v;
        __syncthreads();
        if (tid == 0) {
            float tot = 0.f;
#pragma unroll
            for (int w = 0; w < THREADS / 32; w++) tot += sbestg[w].x;
            float mean = tot * (1.0f / (float)(Bn * CDn * Tn));
            dout[LOSS_OFF]     = mean;
            dout[LOSS_OFF + 1] = mean;
        }
    }
}

// ---------------------------------------------------------------------------
extern "C" void kernel_launch(void* const* d_in, const int* in_sizes, int n_in,
                              void* d_out, int out_size) {
    const float* hid   = (const float*)d_in[0];
    const float* w_in  = (const float*)d_in[1];
    const float* b_in  = (const float*)d_in[2];
    const float* w_out = (const float*)d_in[3];
    const float* b_out = (const float*)d_in[4];
    const float* cb    = (const float*)d_in[5];
    float* dout = (float*)d_out;

    const int smem_bytes = SMEM_FLOATS * 4;  // 76816 B
    cudaFuncSetAttribute(main_kernel, cudaFuncAttributeMaxDynamicSharedMemorySize, smem_bytes);

    main_kernel<<<NBLK, THREADS, smem_bytes>>>(hid, w_in, b_in, w_out, b_out, cb, dout);
}